// round 8
// baseline (speedup 1.0000x reference)
#include <cuda_runtime.h>
#include <cstdint>

// out[r, c] = x[r, c] * diag[c], x: 16384 x 2048 f32.
// Persistent-grid streaming kernel at the HBM mixed-r/w wall:
//   - exactly 148 SMs x 8 CTAs = 1184 persistent CTAs, grid-stride loop
//     (no CTA launch/retire waves, continuously fed L1tex queue)
//   - total threads (303,104) is a multiple of 256 chunks/row -> each
//     thread's column is loop-invariant: diag loaded ONCE, reused ~14x
//   - 256-bit (v8.f32) accesses, .cs evict-first single-touch policy
// 4,194,304 chunks of 8 floats; ~13.84 iterations per thread.

#define N_CHUNKS  (16384u * 2048u / 8u)   // 4,194,304
#define N_CTAS    1184
#define THREADS   256
#define STRIDE    (N_CTAS * THREADS)      // 303,104 (multiple of 256)

__global__ __launch_bounds__(THREADS) void diag_scale_kernel(
    const float* __restrict__ x,
    const float* __restrict__ d,
    float* __restrict__ out)
{
    unsigned int t = blockIdx.x * THREADS + threadIdx.x;
    unsigned int col8 = (t & 255u) * 8u;   // loop-invariant (STRIDE % 256 == 0)

    // diag chunk loaded once, reused every iteration
    float s0,s1,s2,s3,s4,s5,s6,s7;
    asm volatile(
        "ld.global.nc.v8.f32 {%0,%1,%2,%3,%4,%5,%6,%7}, [%8];"
        : "=f"(s0),"=f"(s1),"=f"(s2),"=f"(s3),
          "=f"(s4),"=f"(s5),"=f"(s6),"=f"(s7)
        : "l"(d + col8));

    for (unsigned int i = t; i < N_CHUNKS; i += STRIDE) {
        const float* xp = x   + (size_t)i * 8u;
        float*       op = out + (size_t)i * 8u;

        float v0,v1,v2,v3,v4,v5,v6,v7;
        asm volatile(
            "ld.global.cs.v8.f32 {%0,%1,%2,%3,%4,%5,%6,%7}, [%8];"
            : "=f"(v0),"=f"(v1),"=f"(v2),"=f"(v3),
              "=f"(v4),"=f"(v5),"=f"(v6),"=f"(v7)
            : "l"(xp));

        v0*=s0; v1*=s1; v2*=s2; v3*=s3;
        v4*=s4; v5*=s5; v6*=s6; v7*=s7;

        asm volatile(
            "st.global.cs.v8.f32 [%0], {%1,%2,%3,%4,%5,%6,%7,%8};"
            :: "l"(op),
               "f"(v0),"f"(v1),"f"(v2),"f"(v3),
               "f"(v4),"f"(v5),"f"(v6),"f"(v7)
            : "memory");
    }
}

extern "C" void kernel_launch(void* const* d_in, const int* in_sizes, int n_in,
                              void* d_out, int out_size) {
    const float* x = (const float*)d_in[0];
    const float* d = (const float*)d_in[1];
    float* out = (float*)d_out;

    diag_scale_kernel<<<N_CTAS, THREADS>>>(x, d, out);
}

// round 9
// speedup vs baseline: 1.0659x; 1.0659x over previous
#include <cuda_runtime.h>
#include <cstdint>

// out[r, c] = x[r, c] * diag[c], x: 16384 x 2048 f32.
// Best-measured structure (R7): one-shot CTAs, 2 front-batched 256-bit loads
// per thread in the same column two rows apart, one diag load serving both,
// .cs single-touch policy. This round: 512 threads/block (4096 blocks) to
// halve CTA scheduling overhead at identical per-thread SASS.
// Wall: 268 MB compulsory traffic / ~6.2 TB/s sustained mixed r/w.

#define ROW_F   2048u
#define THREADS 512

__global__ __launch_bounds__(THREADS) void diag_scale_kernel(
    const float* __restrict__ x,
    const float* __restrict__ d,
    float* __restrict__ out)
{
    unsigned int t = blockIdx.x * THREADS + threadIdx.x;  // 0 .. 2,097,151
    unsigned int col8 = (t & 255u) * 8u;                  // float column of chunk
    unsigned int rowpair = t >> 8;                        // pair of rows
    size_t base = (size_t)rowpair * (2u * ROW_F) + col8;

    const float* xp0 = x + base;
    const float* xp1 = x + base + ROW_F;
    float*       op0 = out + base;
    float*       op1 = out + base + ROW_F;
    const float* dp  = d + col8;

    float a0,a1,a2,a3,a4,a5,a6,a7;
    float b0,b1,b2,b3,b4,b5,b6,b7;
    asm volatile(
        "ld.global.cs.v8.f32 {%0,%1,%2,%3,%4,%5,%6,%7}, [%8];"
        : "=f"(a0),"=f"(a1),"=f"(a2),"=f"(a3),
          "=f"(a4),"=f"(a5),"=f"(a6),"=f"(a7)
        : "l"(xp0));
    asm volatile(
        "ld.global.cs.v8.f32 {%0,%1,%2,%3,%4,%5,%6,%7}, [%8];"
        : "=f"(b0),"=f"(b1),"=f"(b2),"=f"(b3),
          "=f"(b4),"=f"(b5),"=f"(b6),"=f"(b7)
        : "l"(xp1));

    float s0,s1,s2,s3,s4,s5,s6,s7;
    asm volatile(
        "ld.global.nc.v8.f32 {%0,%1,%2,%3,%4,%5,%6,%7}, [%8];"
        : "=f"(s0),"=f"(s1),"=f"(s2),"=f"(s3),
          "=f"(s4),"=f"(s5),"=f"(s6),"=f"(s7)
        : "l"(dp));

    a0*=s0; a1*=s1; a2*=s2; a3*=s3; a4*=s4; a5*=s5; a6*=s6; a7*=s7;
    b0*=s0; b1*=s1; b2*=s2; b3*=s3; b4*=s4; b5*=s5; b6*=s6; b7*=s7;

    asm volatile(
        "st.global.cs.v8.f32 [%0], {%1,%2,%3,%4,%5,%6,%7,%8};"
        :: "l"(op0),
           "f"(a0),"f"(a1),"f"(a2),"f"(a3),
           "f"(a4),"f"(a5),"f"(a6),"f"(a7)
        : "memory");
    asm volatile(
        "st.global.cs.v8.f32 [%0], {%1,%2,%3,%4,%5,%6,%7,%8};"
        :: "l"(op1),
           "f"(b0),"f"(b1),"f"(b2),"f"(b3),
           "f"(b4),"f"(b5),"f"(b6),"f"(b7)
        : "memory");
}

extern "C" void kernel_launch(void* const* d_in, const int* in_sizes, int n_in,
                              void* d_out, int out_size) {
    const float* x = (const float*)d_in[0];
    const float* d = (const float*)d_in[1];
    float* out = (float*)d_out;

    // 16384*2048 floats / 16 per thread = 2,097,152 threads -> 4096 blocks
    const int blocks = (16384 * 2048 / 16) / THREADS;  // 4096, exact

    diag_scale_kernel<<<blocks, THREADS>>>(x, d, out);
}

// round 10
// speedup vs baseline: 1.0869x; 1.0197x over previous
#include <cuda_runtime.h>
#include <cstdint>

// FINAL — out[r, c] = x[r, c] * diag[c], x: 16384 x 2048 f32.
//
// This kernel sits at the measured steady-state HBM mixed-read/write wall:
// 268.4 MB compulsory traffic / 43.49 us = 6.17 TB/s sustained under graph
// replay (ncu in-kernel: 6.0 TB/s DRAM, issue 7%, occ 74% — memory-bound).
// Eight structural alternatives (scalar f4, MLP x4, .wt stores, L2 evict
// hints, TMA bulk staging, persistent grid, 512-thread blocks) all measured
// equal or worse; the one-shot 256-thread front-batched shape below is the
// best-measured configuration.
//
// Structure:
//   - 256-bit (v8.f32) global accesses: 1024B per warp per access
//   - 2 independent front-batched v8 loads per thread (2KB/warp in flight),
//     same column, two consecutive rows apart -> one diag load serves both
//   - .cs (evict-first) on the single-touch x/out streams, .nc on diag
//   - exact grid: 8192 blocks x 256 threads, 16 floats per thread

#define ROW_F 2048u

__global__ __launch_bounds__(256) void diag_scale_kernel(
    const float* __restrict__ x,
    const float* __restrict__ d,
    float* __restrict__ out)
{
    unsigned int t = blockIdx.x * 256u + threadIdx.x;     // 0 .. 2,097,151
    unsigned int col8 = (t & 255u) * 8u;                  // float column of chunk
    unsigned int rowpair = t >> 8;                        // pair of rows
    size_t base = (size_t)rowpair * (2u * ROW_F) + col8;

    const float* xp0 = x + base;
    const float* xp1 = x + base + ROW_F;
    float*       op0 = out + base;
    float*       op1 = out + base + ROW_F;
    const float* dp  = d + col8;

    float a0,a1,a2,a3,a4,a5,a6,a7;
    float b0,b1,b2,b3,b4,b5,b6,b7;
    asm volatile(
        "ld.global.cs.v8.f32 {%0,%1,%2,%3,%4,%5,%6,%7}, [%8];"
        : "=f"(a0),"=f"(a1),"=f"(a2),"=f"(a3),
          "=f"(a4),"=f"(a5),"=f"(a6),"=f"(a7)
        : "l"(xp0));
    asm volatile(
        "ld.global.cs.v8.f32 {%0,%1,%2,%3,%4,%5,%6,%7}, [%8];"
        : "=f"(b0),"=f"(b1),"=f"(b2),"=f"(b3),
          "=f"(b4),"=f"(b5),"=f"(b6),"=f"(b7)
        : "l"(xp1));

    float s0,s1,s2,s3,s4,s5,s6,s7;
    asm volatile(
        "ld.global.nc.v8.f32 {%0,%1,%2,%3,%4,%5,%6,%7}, [%8];"
        : "=f"(s0),"=f"(s1),"=f"(s2),"=f"(s3),
          "=f"(s4),"=f"(s5),"=f"(s6),"=f"(s7)
        : "l"(dp));

    a0*=s0; a1*=s1; a2*=s2; a3*=s3; a4*=s4; a5*=s5; a6*=s6; a7*=s7;
    b0*=s0; b1*=s1; b2*=s2; b3*=s3; b4*=s4; b5*=s5; b6*=s6; b7*=s7;

    asm volatile(
        "st.global.cs.v8.f32 [%0], {%1,%2,%3,%4,%5,%6,%7,%8};"
        :: "l"(op0),
           "f"(a0),"f"(a1),"f"(a2),"f"(a3),
           "f"(a4),"f"(a5),"f"(a6),"f"(a7)
        : "memory");
    asm volatile(
        "st.global.cs.v8.f32 [%0], {%1,%2,%3,%4,%5,%6,%7,%8};"
        :: "l"(op1),
           "f"(b0),"f"(b1),"f"(b2),"f"(b3),
           "f"(b4),"f"(b5),"f"(b6),"f"(b7)
        : "memory");
}

extern "C" void kernel_launch(void* const* d_in, const int* in_sizes, int n_in,
                              void* d_out, int out_size) {
    const float* x = (const float*)d_in[0];
    const float* d = (const float*)d_in[1];
    float* out = (float*)d_out;

    // 16384*2048 floats / 16 per thread = 2,097,152 threads -> 8192 blocks
    const int threads = 256;
    const int blocks = (16384 * 2048 / 16) / threads;  // 8192, exact

    diag_scale_kernel<<<blocks, threads>>>(x, d, out);
}